// round 10
// baseline (speedup 1.0000x reference)
#include <cuda_runtime.h>
#include <math.h>

// Problem constants (fixed shapes for this problem instance)
#define N_NODES 100000
#define N_EDGES 1600000
#define HF 128
#define TOT_E (N_EDGES + N_NODES)   // edges + self loops
#define NH (N_NODES * HF)
#define EPS 1e-5f

// ---------------- static device scratch (allocation-free rule) ----------------
__device__ __align__(16) float d_xs[9][NH];  // skip-connection stack
__device__ __align__(16) float d_tmp[NH];    // GEMM output / agg input
__device__ __align__(16) float d_agg[NH];    // agg output / BN input
__device__ __align__(16) float d_hA[NH];
__device__ __align__(16) float d_hB[NH];
__device__ int   d_deg[N_NODES];
__device__ float d_dinv[N_NODES];
__device__ int   d_offs[N_NODES + 1];
__device__ int   d_cursor[N_NODES];
__device__ int   d_csrs[TOT_E];              // src node per CSR slot
__device__ __align__(16) float d_csrn[TOT_E];// norm per CSR slot
__device__ int   d_part[128];                // scan partials
__device__ __align__(16) float d_sum[HF];    // BN sum accumulators
__device__ __align__(16) float d_sq[HF];     // BN sumsq accumulators
__device__ float d_t1[N_NODES];              // last-layer scalar pre-aggregation
__device__ int   d_stride;                   // 1: edge_index is int32, 2: int64

// Buffer selector: 0..8 -> xs[k], 9 -> hA, 10 -> hB. Resolved device-side so the
// host launcher never needs cudaGetSymbolAddress (not capture-legal).
__device__ __forceinline__ float* sel_buf(int k) {
    if (k < 9)   return d_xs[k];
    if (k == 9)  return d_hA;
    return d_hB;
}

// ---------------- edge_index dtype detection ----------------
// View the buffer as int32 words. int64 (little-endian, values in [0, 2^31)):
// every odd word of the first half is a zero high-word. int32: odd words are
// random node ids. Sample 64 odd words inside the always-valid first 2E words.
__global__ void detect_dtype_k(const int* __restrict__ ei, int E) {
    if (threadIdx.x == 0 && blockIdx.x == 0) {
        long long total = 2LL * E;               // words guaranteed valid
        long long step = total / 64;
        int all_zero = 1;
        for (int k = 0; k < 64; k++) {
            long long pos = ((long long)k * step) | 1;   // odd word
            if (pos >= total) pos = total - 1 - ((total & 1) ? 0 : 1);
            if (ei[pos] != 0) { all_zero = 0; break; }
        }
        d_stride = all_zero ? 2 : 1;
    }
}

__device__ __forceinline__ int edge_src(const int* ei, int E, int e) {
    return (d_stride == 2) ? ei[2 * e] : ei[e];
}
__device__ __forceinline__ int edge_dst(const int* ei, int E, int e) {
    return (d_stride == 2) ? ei[2 * (E + e)] : ei[E + e];
}

// ---------------- preprocessing kernels ----------------
__global__ void init_deg_k(int n) {
    int i = blockIdx.x * blockDim.x + threadIdx.x;
    if (i < n) d_deg[i] = 1;   // self loop
}

__global__ void count_deg_k(const int* __restrict__ ei, int E) {
    int e = blockIdx.x * blockDim.x + threadIdx.x;
    if (e < E) atomicAdd(&d_deg[edge_dst(ei, E, e)], 1);
}

__global__ void dinv_k(int n) {
    int i = blockIdx.x * blockDim.x + threadIdx.x;
    if (i < n) d_dinv[i] = rsqrtf((float)d_deg[i]);
}

// exclusive scan of d_deg -> d_offs (block-local), per-block totals to d_part
__global__ void scanA_k(int n) {
    __shared__ int s[1024];
    int i = blockIdx.x * 1024 + threadIdx.x;
    int v = (i < n) ? d_deg[i] : 0;
    s[threadIdx.x] = v;
    __syncthreads();
    for (int d = 1; d < 1024; d <<= 1) {
        int t = (threadIdx.x >= d) ? s[threadIdx.x - d] : 0;
        __syncthreads();
        s[threadIdx.x] += t;
        __syncthreads();
    }
    if (i < n) d_offs[i] = s[threadIdx.x] - v;   // exclusive within block
    if (threadIdx.x == 1023) d_part[blockIdx.x] = s[1023];
}

__global__ void scanB_k(int nb) {
    if (threadIdx.x == 0) {
        int run = 0;
        for (int i = 0; i < nb; i++) { int t = d_part[i]; d_part[i] = run; run += t; }
    }
}

// finalize offsets, place self-loop entries, init cursors
__global__ void scanC_k(int n, int total) {
    int i = blockIdx.x * blockDim.x + threadIdx.x;
    if (i < n) {
        int o = d_offs[i] + d_part[i >> 10];
        d_offs[i] = o;
        float dv = d_dinv[i];
        d_csrs[o] = i;
        d_csrn[o] = dv * dv;
        d_cursor[i] = o + 1;
    }
    if (i == 0) d_offs[n] = total;
}

__global__ void scatter_k(const int* __restrict__ ei, int E) {
    int e = blockIdx.x * blockDim.x + threadIdx.x;
    if (e < E) {
        int s = edge_src(ei, E, e);
        int d = edge_dst(ei, E, e);
        int p = atomicAdd(&d_cursor[d], 1);
        d_csrs[p] = s;
        d_csrn[p] = d_dinv[s] * d_dinv[d];
    }
}

// ---------------- per-layer kernels ----------------
__global__ void zero_stats_k() {
    int t = threadIdx.x;
    if (t < HF) { d_sum[t] = 0.f; d_sq[t] = 0.f; }
}

// first layer: d_tmp = x[N,3] @ W0[3,128]
__global__ void gemm3_k(const float* __restrict__ x, const float* __restrict__ W0,
                        int n) {
    int i = blockIdx.x * blockDim.x + threadIdx.x;   // one thread per (node, 4 cols)
    if (i >= n * 32) return;
    int v = i >> 5;
    int c = (i & 31) << 2;
    float x0 = x[v * 3 + 0], x1 = x[v * 3 + 1], x2 = x[v * 3 + 2];
    float4 w0 = *(const float4*)&W0[c];
    float4 w1 = *(const float4*)&W0[HF + c];
    float4 w2 = *(const float4*)&W0[2 * HF + c];
    float4 o;
    o.x = x0 * w0.x + x1 * w1.x + x2 * w2.x;
    o.y = x0 * w0.y + x1 * w1.y + x2 * w2.y;
    o.z = x0 * w0.z + x1 * w1.z + x2 * w2.z;
    o.w = x0 * w0.w + x1 * w1.w + x2 * w2.w;
    *(float4*)&d_tmp[v * HF + c] = o;
}

// d_tmp[N,128] = (sel(aSel) [+ sel(bSel)]) @ W[128,128], fp32.
// Block: 64 rows x 128 cols, 256 threads, 4x8 acc per thread.
__global__ void __launch_bounds__(256)
gemm128_k(int aSel, int bSel, const float* __restrict__ W, int n) {
    __shared__ float As[64][36];   // row stride 144B (multiple of 16) -> float4-legal
    __shared__ float Ws[32][HF];
    const float* A = sel_buf(aSel);
    const float* B = (bSel >= 0) ? sel_buf(bSel) : (const float*)0;
    int brow = blockIdx.x * 64;
    int tid = threadIdx.x;
    int r0 = (tid >> 4) << 2;      // 0..60 step 4
    int c0 = (tid & 15) << 3;      // 0..120 step 8
    float acc[4][8];
#pragma unroll
    for (int i = 0; i < 4; i++)
#pragma unroll
        for (int j = 0; j < 8; j++) acc[i][j] = 0.f;

    for (int k0 = 0; k0 < HF; k0 += 32) {
        // stage W chunk: 32x128 = 1024 float4
#pragma unroll
        for (int i = 0; i < 4; i++) {
            int idx = tid + i * 256;
            int kr = idx >> 5;
            int cc = (idx & 31) << 2;
            *(float4*)&Ws[kr][cc] = *(const float4*)&W[(k0 + kr) * HF + cc];
        }
        // stage A chunk: 64x32 = 512 float4 (skip-add fused here)
#pragma unroll
        for (int i = 0; i < 2; i++) {
            int idx = tid + i * 256;
            int ar = idx >> 3;
            int ac = (idx & 7) << 2;
            int grow = brow + ar;
            float4 v = make_float4(0.f, 0.f, 0.f, 0.f);
            if (grow < n) {
                v = *(const float4*)&A[(size_t)grow * HF + k0 + ac];
                if (B) {
                    float4 w = *(const float4*)&B[(size_t)grow * HF + k0 + ac];
                    v.x += w.x; v.y += w.y; v.z += w.z; v.w += w.w;
                }
            }
            *(float4*)&As[ar][ac] = v;
        }
        __syncthreads();
#pragma unroll
        for (int kk = 0; kk < 32; kk++) {
            float a0 = As[r0 + 0][kk];
            float a1 = As[r0 + 1][kk];
            float a2 = As[r0 + 2][kk];
            float a3 = As[r0 + 3][kk];
            float4 b0 = *(float4*)&Ws[kk][c0];
            float4 b1 = *(float4*)&Ws[kk][c0 + 4];
            float bb[8] = {b0.x, b0.y, b0.z, b0.w, b1.x, b1.y, b1.z, b1.w};
#pragma unroll
            for (int j = 0; j < 8; j++) {
                acc[0][j] += a0 * bb[j];
                acc[1][j] += a1 * bb[j];
                acc[2][j] += a2 * bb[j];
                acc[3][j] += a3 * bb[j];
            }
        }
        __syncthreads();
    }
#pragma unroll
    for (int i = 0; i < 4; i++) {
        int grow = brow + r0 + i;
        if (grow < n) {
            float4 o0 = make_float4(acc[i][0], acc[i][1], acc[i][2], acc[i][3]);
            float4 o1 = make_float4(acc[i][4], acc[i][5], acc[i][6], acc[i][7]);
            *(float4*)&d_tmp[(size_t)grow * HF + c0] = o0;
            *(float4*)&d_tmp[(size_t)grow * HF + c0 + 4] = o1;
        }
    }
}

// aggregation: d_agg[v] = sum_{csr} norm * d_tmp[src]; warp per node, lane owns
// 4 features. Fused BN stats (per-feature sum/sumsq) via warp partials + atomics.
__global__ void agg128_k(int n) {
    int gw = (blockIdx.x * blockDim.x + threadIdx.x) >> 5;
    int lane = threadIdx.x & 31;
    int nwarps = (gridDim.x * blockDim.x) >> 5;
    float4 ssum = make_float4(0.f, 0.f, 0.f, 0.f);
    float4 ssq  = make_float4(0.f, 0.f, 0.f, 0.f);
    for (int v = gw; v < n; v += nwarps) {
        int b = d_offs[v], e = d_offs[v + 1];
        float4 acc = make_float4(0.f, 0.f, 0.f, 0.f);
        int i = b;
        for (; i + 1 < e; i += 2) {
            int   s0 = d_csrs[i],     s1 = d_csrs[i + 1];
            float n0 = d_csrn[i],     n1 = d_csrn[i + 1];
            float4 v0 = __ldg((const float4*)&d_tmp[(size_t)s0 * HF + lane * 4]);
            float4 v1 = __ldg((const float4*)&d_tmp[(size_t)s1 * HF + lane * 4]);
            acc.x += n0 * v0.x + n1 * v1.x;
            acc.y += n0 * v0.y + n1 * v1.y;
            acc.z += n0 * v0.z + n1 * v1.z;
            acc.w += n0 * v0.w + n1 * v1.w;
        }
        if (i < e) {
            int s0 = d_csrs[i];
            float n0 = d_csrn[i];
            float4 v0 = __ldg((const float4*)&d_tmp[(size_t)s0 * HF + lane * 4]);
            acc.x += n0 * v0.x; acc.y += n0 * v0.y;
            acc.z += n0 * v0.z; acc.w += n0 * v0.w;
        }
        *(float4*)&d_agg[(size_t)v * HF + lane * 4] = acc;
        ssum.x += acc.x; ssum.y += acc.y; ssum.z += acc.z; ssum.w += acc.w;
        ssq.x += acc.x * acc.x; ssq.y += acc.y * acc.y;
        ssq.z += acc.z * acc.z; ssq.w += acc.w * acc.w;
    }
    int f = lane * 4;
    atomicAdd(&d_sum[f + 0], ssum.x); atomicAdd(&d_sum[f + 1], ssum.y);
    atomicAdd(&d_sum[f + 2], ssum.z); atomicAdd(&d_sum[f + 3], ssum.w);
    atomicAdd(&d_sq[f + 0], ssq.x);  atomicAdd(&d_sq[f + 1], ssq.y);
    atomicAdd(&d_sq[f + 2], ssq.z);  atomicAdd(&d_sq[f + 3], ssq.w);
}

// BN (training-mode biased stats) + ReLU: sel(dstSel) = relu(bn(d_agg))
__global__ void bnrelu_k(int dstSel, const float* __restrict__ g,
                         const float* __restrict__ b, float invN, int n4) {
    int i = blockIdx.x * blockDim.x + threadIdx.x;
    if (i >= n4) return;
    float* h = sel_buf(dstSel);
    int f4 = i & 31;
    float4 s  = *(const float4*)&d_sum[f4 * 4];
    float4 q  = *(const float4*)&d_sq[f4 * 4];
    float4 gg = *(const float4*)&g[f4 * 4];
    float4 bb = *(const float4*)&b[f4 * 4];
    float4 x  = *(const float4*)&d_agg[(size_t)i * 4];
    float m, vv, sc, o;
    m = s.x * invN; vv = q.x * invN - m * m; sc = rsqrtf(vv + EPS) * gg.x;
    o = (x.x - m) * sc + bb.x; x.x = fmaxf(o, 0.f);
    m = s.y * invN; vv = q.y * invN - m * m; sc = rsqrtf(vv + EPS) * gg.y;
    o = (x.y - m) * sc + bb.y; x.y = fmaxf(o, 0.f);
    m = s.z * invN; vv = q.z * invN - m * m; sc = rsqrtf(vv + EPS) * gg.z;
    o = (x.z - m) * sc + bb.z; x.z = fmaxf(o, 0.f);
    m = s.w * invN; vv = q.w * invN - m * m; sc = rsqrtf(vv + EPS) * gg.w;
    o = (x.w - m) * sc + bb.w; x.w = fmaxf(o, 0.f);
    *(float4*)&h[(size_t)i * 4] = x;
}

// last layer: d_t1[v] = dot(sel(hSel)[v] + xs[0][v], Wout)   (warp per node)
__global__ void dot_out_k(int hSel, const float* __restrict__ Wv, int n) {
    int w = (blockIdx.x * blockDim.x + threadIdx.x) >> 5;
    int lane = threadIdx.x & 31;
    if (w >= n) return;
    const float* h = sel_buf(hSel);
    float4 a = *(const float4*)&h[(size_t)w * HF + lane * 4];
    float4 b = *(const float4*)&d_xs[0][(size_t)w * HF + lane * 4];
    float4 ww = *(const float4*)&Wv[lane * 4];
    float s = (a.x + b.x) * ww.x + (a.y + b.y) * ww.y +
              (a.z + b.z) * ww.z + (a.w + b.w) * ww.w;
#pragma unroll
    for (int o = 16; o; o >>= 1) s += __shfl_down_sync(0xffffffffu, s, o);
    if (lane == 0) d_t1[w] = s;
}

__global__ void agg_sig_k(float* __restrict__ out, int n) {
    int v = blockIdx.x * blockDim.x + threadIdx.x;
    if (v >= n) return;
    int b = d_offs[v], e = d_offs[v + 1];
    float s = 0.f;
    for (int i = b; i < e; i++) s += d_csrn[i] * d_t1[d_csrs[i]];
    out[v] = 1.0f / (1.0f + expf(-s));
}

// ---------------- launcher (kernel launches ONLY — graph-capture safe) ----------------
extern "C" void kernel_launch(void* const* d_in, const int* in_sizes, int n_in,
                              void* d_out, int out_size) {
    const float* x    = (const float*)d_in[0];
    const int*   ei   = (const int*)d_in[1];     // int32 or int64 — detected on device
    const float* W0   = (const float*)d_in[2];
    const float* Ws1  = (const float*)d_in[3];
    const float* g1   = (const float*)d_in[4];
    const float* b1   = (const float*)d_in[5];
    const float* Ws2  = (const float*)d_in[6];
    const float* g2   = (const float*)d_in[7];
    const float* b2   = (const float*)d_in[8];
    const float* Wout = (const float*)d_in[9];
    float* out = (float*)d_out;

    const int N = in_sizes[0] / 3;
    const int E = in_sizes[1] / 2;

    const float invN = 1.0f / (float)N;
    const int TB = 256;
    const int gN    = (N + TB - 1) / TB;
    const int gE    = (E + TB - 1) / TB;
    const int g32   = (N * 32 + TB - 1) / TB;    // elementwise over N*128/4
    const int gGemm = (N + 63) / 64;
    const int nb    = (N + 1023) / 1024;

    // --- graph preprocessing (CSR by dst, norms, self loops) ---
    detect_dtype_k<<<1, 32>>>(ei, E);
    init_deg_k<<<gN, TB>>>(N);
    count_deg_k<<<gE, TB>>>(ei, E);
    dinv_k<<<gN, TB>>>(N);
    scanA_k<<<nb, 1024>>>(N);
    scanB_k<<<1, 32>>>(nb);
    scanC_k<<<gN, TB>>>(N, E + N);
    scatter_k<<<gE, TB>>>(ei, E);

    // --- layer 0: conv1[0] -> xs[0] ---
    gemm3_k<<<g32, TB>>>(x, W0, N);
    zero_stats_k<<<1, 128>>>();
    agg128_k<<<2048, TB>>>(N);
    bnrelu_k<<<g32, TB>>>(0, g1, b1, invN, N * 32);
    int cur = 0;

    // --- up phase: i = 1..9 ---
    for (int i = 1; i <= 9; i++) {
        gemm128_k<<<gGemm, TB>>>(cur, -1, Ws1 + (size_t)(i - 1) * HF * HF, N);
        zero_stats_k<<<1, 128>>>();
        agg128_k<<<2048, TB>>>(N);
        int dst = (i < 9) ? i : 9;               // xs[i] or hA
        bnrelu_k<<<g32, TB>>>(dst, g1 + (size_t)i * HF, b1 + (size_t)i * HF,
                              invN, N * 32);
        cur = dst;
    }

    // --- down phase: i = 0..7 (skip-add fused into GEMM A-load) ---
    int h = 9;                                    // hA
    for (int i = 0; i < 8; i++) {
        int j = 8 - i;
        gemm128_k<<<gGemm, TB>>>(h, j, Ws2 + (size_t)i * HF * HF, N);
        zero_stats_k<<<1, 128>>>();
        agg128_k<<<2048, TB>>>(N);
        int nh = (h == 9) ? 10 : 9;
        bnrelu_k<<<g32, TB>>>(nh, g2 + (size_t)i * HF, b2 + (size_t)i * HF,
                              invN, N * 32);
        h = nh;
    }

    // --- final: h = h + xs[0]; out = sigmoid(conv(h, Wout)) ---
    dot_out_k<<<g32, TB>>>(h, Wout, N);
    agg_sig_k<<<gN, TB>>>(out, N);
}

// round 11
// speedup vs baseline: 1.4548x; 1.4548x over previous
#include <cuda_runtime.h>
#include <math.h>

// Problem constants (fixed shapes for this problem instance)
#define N_NODES 100000
#define N_EDGES 1600000
#define HF 128
#define TOT_E (N_EDGES + N_NODES)   // edges + self loops
#define NH (N_NODES * HF)
#define EPS 1e-5f
#define NSTATS 18

// ---------------- static device scratch (allocation-free rule) ----------------
__device__ __align__(16) float d_xs[9][NH];  // skip stack (RAW agg outputs)
__device__ __align__(16) float d_tmp[NH];    // GEMM output / agg input
__device__ __align__(16) float d_hA[NH];     // RAW agg outputs (ping/pong)
__device__ __align__(16) float d_hB[NH];
__device__ int   d_deg[N_NODES];
__device__ float d_dinv[N_NODES];
__device__ int   d_offs[N_NODES + 1];
__device__ int   d_cursor[N_NODES];
__device__ __align__(16) int2 d_csr2[TOT_E]; // (src, norm-bits) per CSR slot
__device__ int   d_part[128];                // scan partials
__device__ __align__(16) float d_sums[NSTATS][HF];
__device__ __align__(16) float d_sqs[NSTATS][HF];
__device__ __align__(16) float d_bnsc[NSTATS][HF];  // precomputed BN scale
__device__ __align__(16) float d_bnsh[NSTATS][HF];  // precomputed BN shift
__device__ float d_t1[N_NODES];              // last-layer scalar pre-aggregation
__device__ int   d_stride;                   // 1: edge_index int32, 2: int64

// Buffer selector: 0..8 -> xs[k], 9 -> hA, 10 -> hB (device-side; no symbol
// resolution on host — not capture-legal).
__device__ __forceinline__ float* sel_buf(int k) {
    if (k < 9)   return d_xs[k];
    if (k == 9)  return d_hA;
    return d_hB;
}

// packed fp32x2 fma (sm_100+): d = a*b + d on two lanes at once
__device__ __forceinline__ void fma2(unsigned long long& d,
                                     unsigned long long a, unsigned long long b) {
    asm("fma.rn.f32x2 %0, %1, %2, %0;" : "+l"(d) : "l"(a), "l"(b));
}
__device__ __forceinline__ unsigned long long splat2(float f) {
    unsigned long long p;
    unsigned int u = __float_as_uint(f);
    asm("mov.b64 %0, {%1, %1};" : "=l"(p) : "r"(u));
    return p;
}

// ---------------- edge_index dtype detection ----------------
__global__ void detect_dtype_k(const int* __restrict__ ei, int E) {
    if (threadIdx.x == 0 && blockIdx.x == 0) {
        long long total = 2LL * E;
        long long step = total / 64;
        int all_zero = 1;
        for (int k = 0; k < 64; k++) {
            long long pos = ((long long)k * step) | 1;   // odd word
            if (pos >= total) pos = total - 1 - ((total & 1) ? 0 : 1);
            if (ei[pos] != 0) { all_zero = 0; break; }
        }
        d_stride = all_zero ? 2 : 1;
    }
}
__device__ __forceinline__ int edge_src(const int* ei, int E, int e) {
    return (d_stride == 2) ? ei[2 * e] : ei[e];
}
__device__ __forceinline__ int edge_dst(const int* ei, int E, int e) {
    return (d_stride == 2) ? ei[2 * (E + e)] : ei[E + e];
}

// ---------------- preprocessing ----------------
__global__ void init_deg_k(int n) {
    int i = blockIdx.x * blockDim.x + threadIdx.x;
    if (i < n) d_deg[i] = 1;   // self loop
}
__global__ void count_deg_k(const int* __restrict__ ei, int E) {
    int e = blockIdx.x * blockDim.x + threadIdx.x;
    if (e < E) atomicAdd(&d_deg[edge_dst(ei, E, e)], 1);
}
__global__ void dinv_k(int n) {
    int i = blockIdx.x * blockDim.x + threadIdx.x;
    if (i < n) d_dinv[i] = rsqrtf((float)d_deg[i]);
}
__global__ void scanA_k(int n) {
    __shared__ int s[1024];
    int i = blockIdx.x * 1024 + threadIdx.x;
    int v = (i < n) ? d_deg[i] : 0;
    s[threadIdx.x] = v;
    __syncthreads();
    for (int d = 1; d < 1024; d <<= 1) {
        int t = (threadIdx.x >= d) ? s[threadIdx.x - d] : 0;
        __syncthreads();
        s[threadIdx.x] += t;
        __syncthreads();
    }
    if (i < n) d_offs[i] = s[threadIdx.x] - v;
    if (threadIdx.x == 1023) d_part[blockIdx.x] = s[1023];
}
__global__ void scanB_k(int nb) {
    if (threadIdx.x == 0) {
        int run = 0;
        for (int i = 0; i < nb; i++) { int t = d_part[i]; d_part[i] = run; run += t; }
    }
}
__global__ void scanC_k(int n, int total) {
    int i = blockIdx.x * blockDim.x + threadIdx.x;
    if (i < n) {
        int o = d_offs[i] + d_part[i >> 10];
        d_offs[i] = o;
        float dv = d_dinv[i];
        d_csr2[o] = make_int2(i, __float_as_int(dv * dv));
        d_cursor[i] = o + 1;
    }
    if (i == 0) d_offs[n] = total;
}
__global__ void scatter_k(const int* __restrict__ ei, int E) {
    int e = blockIdx.x * blockDim.x + threadIdx.x;
    if (e < E) {
        int s = edge_src(ei, E, e);
        int d = edge_dst(ei, E, e);
        int p = atomicAdd(&d_cursor[d], 1);
        d_csr2[p] = make_int2(s, __float_as_int(d_dinv[s] * d_dinv[d]));
    }
}
__global__ void zero_all_stats_k() {
    int i = blockIdx.x * blockDim.x + threadIdx.x;
    if (i < NSTATS * HF) {
        ((float*)d_sums)[i] = 0.f;
        ((float*)d_sqs)[i] = 0.f;
    }
}

// ---------------- per-layer kernels ----------------
// BN params for stat slot l (biased batch stats, matching reference)
__global__ void bnparam_k(int l, const float* __restrict__ g,
                          const float* __restrict__ b, float invN) {
    int t = threadIdx.x;
    if (t < HF) {
        float m = d_sums[l][t] * invN;
        float v = d_sqs[l][t] * invN - m * m;
        float sc = rsqrtf(v + EPS) * g[t];
        d_bnsc[l][t] = sc;
        d_bnsh[l][t] = b[t] - m * sc;
    }
}

// first layer: d_tmp = x[N,3] @ W0[3,128]   (raw input, no BN)
__global__ void gemm3_k(const float* __restrict__ x, const float* __restrict__ W0,
                        int n) {
    int i = blockIdx.x * blockDim.x + threadIdx.x;
    if (i >= n * 32) return;
    int v = i >> 5;
    int c = (i & 31) << 2;
    float x0 = x[v * 3 + 0], x1 = x[v * 3 + 1], x2 = x[v * 3 + 2];
    float4 w0 = *(const float4*)&W0[c];
    float4 w1 = *(const float4*)&W0[HF + c];
    float4 w2 = *(const float4*)&W0[2 * HF + c];
    float4 o;
    o.x = x0 * w0.x + x1 * w1.x + x2 * w2.x;
    o.y = x0 * w0.y + x1 * w1.y + x2 * w2.y;
    o.z = x0 * w0.z + x1 * w1.z + x2 * w2.z;
    o.w = x0 * w0.w + x1 * w1.w + x2 * w2.w;
    *(float4*)&d_tmp[v * HF + c] = o;
}

// d_tmp[N,128] = (relu(bn_a(A)) [+ relu(bn_b(B))]) @ W[128,128]
// Tile 128x128x16, 256 threads, 8x8 microtile, packed f32x2 FMA.
#define BM 128
#define BK 16
__global__ void __launch_bounds__(256, 2)
gemm128_k(int aSel, int aStat, int bSel, int bStat,
          const float* __restrict__ W, int n) {
    __shared__ __align__(16) float As[BM][20];   // 80B row stride (16B multiple)
    __shared__ __align__(16) float Ws[BK][HF];
    __shared__ __align__(16) float scA[HF], shA[HF], scB[HF], shB[HF];
    const float* A = sel_buf(aSel);
    const float* B = (bSel >= 0) ? sel_buf(bSel) : (const float*)0;
    int tid = threadIdx.x;
    if (tid < HF) {
        scA[tid] = d_bnsc[aStat][tid];
        shA[tid] = d_bnsh[aStat][tid];
        if (bSel >= 0) { scB[tid] = d_bnsc[bStat][tid]; shB[tid] = d_bnsh[bStat][tid]; }
    }
    int brow = blockIdx.x * BM;
    int r0 = (tid >> 4) << 3;      // 0..120 step 8
    int c0 = (tid & 15) << 3;      // 0..120 step 8
    unsigned long long acc[8][4];
#pragma unroll
    for (int r = 0; r < 8; r++)
#pragma unroll
        for (int j = 0; j < 4; j++) acc[r][j] = 0ULL;
    __syncthreads();

    for (int k0 = 0; k0 < HF; k0 += BK) {
        // stage A: 128x16 floats = 512 float4, bn+relu (+skip) fused
#pragma unroll
        for (int i = 0; i < 2; i++) {
            int idx = tid + i * 256;
            int ar = idx >> 2;
            int ac = (idx & 3) << 2;
            int grow = brow + ar;
            int f = k0 + ac;
            float4 v = make_float4(0.f, 0.f, 0.f, 0.f);
            if (grow < n) {
                float4 a4 = *(const float4*)&A[(size_t)grow * HF + f];
                float4 sa = *(float4*)&scA[f];
                float4 ha = *(float4*)&shA[f];
                v.x = fmaxf(fmaf(a4.x, sa.x, ha.x), 0.f);
                v.y = fmaxf(fmaf(a4.y, sa.y, ha.y), 0.f);
                v.z = fmaxf(fmaf(a4.z, sa.z, ha.z), 0.f);
                v.w = fmaxf(fmaf(a4.w, sa.w, ha.w), 0.f);
                if (B) {
                    float4 b4 = *(const float4*)&B[(size_t)grow * HF + f];
                    float4 sb = *(float4*)&scB[f];
                    float4 hb = *(float4*)&shB[f];
                    v.x += fmaxf(fmaf(b4.x, sb.x, hb.x), 0.f);
                    v.y += fmaxf(fmaf(b4.y, sb.y, hb.y), 0.f);
                    v.z += fmaxf(fmaf(b4.z, sb.z, hb.z), 0.f);
                    v.w += fmaxf(fmaf(b4.w, sb.w, hb.w), 0.f);
                }
            }
            *(float4*)&As[ar][ac] = v;
        }
        // stage W: 16x128 = 512 float4
#pragma unroll
        for (int i = 0; i < 2; i++) {
            int idx = tid + i * 256;
            int kr = idx >> 5;
            int cc = (idx & 31) << 2;
            *(float4*)&Ws[kr][cc] = *(const float4*)&W[(size_t)(k0 + kr) * HF + cc];
        }
        __syncthreads();
#pragma unroll
        for (int kk = 0; kk < BK; kk++) {
            ulonglong2 t0 = *(ulonglong2*)&Ws[kk][c0];
            ulonglong2 t1 = *(ulonglong2*)&Ws[kk][c0 + 4];
            unsigned long long bp0 = t0.x, bp1 = t0.y, bp2 = t1.x, bp3 = t1.y;
#pragma unroll
            for (int r = 0; r < 8; r++) {
                unsigned long long ap = splat2(As[r0 + r][kk]);
                fma2(acc[r][0], ap, bp0);
                fma2(acc[r][1], ap, bp1);
                fma2(acc[r][2], ap, bp2);
                fma2(acc[r][3], ap, bp3);
            }
        }
        __syncthreads();
    }
#pragma unroll
    for (int r = 0; r < 8; r++) {
        int grow = brow + r0 + r;
        if (grow < n) {
            *(ulonglong2*)&d_tmp[(size_t)grow * HF + c0] =
                make_ulonglong2(acc[r][0], acc[r][1]);
            *(ulonglong2*)&d_tmp[(size_t)grow * HF + c0 + 4] =
                make_ulonglong2(acc[r][2], acc[r][3]);
        }
    }
}

// aggregation: sel(dstSel)[v] = sum_{csr} norm * d_tmp[src]; warp/node, lane=4 feats.
// Fused BN stats into d_sums/d_sqs[statIdx]. Unroll-4 for MLP.
__global__ void agg128_k(int n, int dstSel, int statIdx) {
    float* dst = sel_buf(dstSel);
    const float4* T = (const float4*)d_tmp;
    int gw = (blockIdx.x * blockDim.x + threadIdx.x) >> 5;
    int lane = threadIdx.x & 31;
    int nwarps = (gridDim.x * blockDim.x) >> 5;
    float4 ssum = make_float4(0.f, 0.f, 0.f, 0.f);
    float4 ssq  = make_float4(0.f, 0.f, 0.f, 0.f);
    for (int v = gw; v < n; v += nwarps) {
        int b = d_offs[v], e = d_offs[v + 1];
        float4 acc = make_float4(0.f, 0.f, 0.f, 0.f);
        int i = b;
        for (; i + 4 <= e; i += 4) {
            int2 c0 = d_csr2[i],     c1 = d_csr2[i + 1];
            int2 c2 = d_csr2[i + 2], c3 = d_csr2[i + 3];
            float4 v0 = __ldg(&T[(size_t)c0.x * 32 + lane]);
            float4 v1 = __ldg(&T[(size_t)c1.x * 32 + lane]);
            float4 v2 = __ldg(&T[(size_t)c2.x * 32 + lane]);
            float4 v3 = __ldg(&T[(size_t)c3.x * 32 + lane]);
            float n0 = __int_as_float(c0.y), n1 = __int_as_float(c1.y);
            float n2 = __int_as_float(c2.y), n3 = __int_as_float(c3.y);
            acc.x += n0 * v0.x + n1 * v1.x + n2 * v2.x + n3 * v3.x;
            acc.y += n0 * v0.y + n1 * v1.y + n2 * v2.y + n3 * v3.y;
            acc.z += n0 * v0.z + n1 * v1.z + n2 * v2.z + n3 * v3.z;
            acc.w += n0 * v0.w + n1 * v1.w + n2 * v2.w + n3 * v3.w;
        }
        for (; i < e; i++) {
            int2 c = d_csr2[i];
            float4 v0 = __ldg(&T[(size_t)c.x * 32 + lane]);
            float nn = __int_as_float(c.y);
            acc.x += nn * v0.x; acc.y += nn * v0.y;
            acc.z += nn * v0.z; acc.w += nn * v0.w;
        }
        *(float4*)&dst[(size_t)v * HF + lane * 4] = acc;
        ssum.x += acc.x; ssum.y += acc.y; ssum.z += acc.z; ssum.w += acc.w;
        ssq.x += acc.x * acc.x; ssq.y += acc.y * acc.y;
        ssq.z += acc.z * acc.z; ssq.w += acc.w * acc.w;
    }
    int f = lane * 4;
    atomicAdd(&d_sums[statIdx][f + 0], ssum.x);
    atomicAdd(&d_sums[statIdx][f + 1], ssum.y);
    atomicAdd(&d_sums[statIdx][f + 2], ssum.z);
    atomicAdd(&d_sums[statIdx][f + 3], ssum.w);
    atomicAdd(&d_sqs[statIdx][f + 0], ssq.x);
    atomicAdd(&d_sqs[statIdx][f + 1], ssq.y);
    atomicAdd(&d_sqs[statIdx][f + 2], ssq.z);
    atomicAdd(&d_sqs[statIdx][f + 3], ssq.w);
}

// last layer: t1[v] = dot(relu(bn_h(h[v])) + relu(bn_0(xs0[v])), Wout)
__global__ void dot_out_k(int hSel, int hStat, const float* __restrict__ Wv, int n) {
    int w = (blockIdx.x * blockDim.x + threadIdx.x) >> 5;
    int lane = threadIdx.x & 31;
    if (w >= n) return;
    const float* h = sel_buf(hSel);
    int f = lane * 4;
    float4 a  = *(const float4*)&h[(size_t)w * HF + f];
    float4 b  = *(const float4*)&d_xs[0][(size_t)w * HF + f];
    float4 sh_ = *(float4*)&d_bnsc[hStat][f];
    float4 hh  = *(float4*)&d_bnsh[hStat][f];
    float4 s0  = *(float4*)&d_bnsc[0][f];
    float4 h0  = *(float4*)&d_bnsh[0][f];
    float4 ww = *(const float4*)&Wv[f];
    float sx = fmaxf(fmaf(a.x, sh_.x, hh.x), 0.f) + fmaxf(fmaf(b.x, s0.x, h0.x), 0.f);
    float sy = fmaxf(fmaf(a.y, sh_.y, hh.y), 0.f) + fmaxf(fmaf(b.y, s0.y, h0.y), 0.f);
    float sz = fmaxf(fmaf(a.z, sh_.z, hh.z), 0.f) + fmaxf(fmaf(b.z, s0.z, h0.z), 0.f);
    float sw = fmaxf(fmaf(a.w, sh_.w, hh.w), 0.f) + fmaxf(fmaf(b.w, s0.w, h0.w), 0.f);
    float s = sx * ww.x + sy * ww.y + sz * ww.z + sw * ww.w;
#pragma unroll
    for (int o = 16; o; o >>= 1) s += __shfl_down_sync(0xffffffffu, s, o);
    if (lane == 0) d_t1[w] = s;
}

__global__ void agg_sig_k(float* __restrict__ out, int n) {
    int v = blockIdx.x * blockDim.x + threadIdx.x;
    if (v >= n) return;
    int b = d_offs[v], e = d_offs[v + 1];
    float s = 0.f;
    for (int i = b; i < e; i++)
        s += __int_as_float(d_csr2[i].y) * d_t1[d_csr2[i].x];
    out[v] = 1.0f / (1.0f + expf(-s));
}

// ---------------- launcher (kernel launches ONLY — graph-capture safe) ----------------
extern "C" void kernel_launch(void* const* d_in, const int* in_sizes, int n_in,
                              void* d_out, int out_size) {
    const float* x    = (const float*)d_in[0];
    const int*   ei   = (const int*)d_in[1];     // int32 or int64, device-detected
    const float* W0   = (const float*)d_in[2];
    const float* Ws1  = (const float*)d_in[3];
    const float* g1   = (const float*)d_in[4];
    const float* b1   = (const float*)d_in[5];
    const float* Ws2  = (const float*)d_in[6];
    const float* g2   = (const float*)d_in[7];
    const float* b2   = (const float*)d_in[8];
    const float* Wout = (const float*)d_in[9];
    float* out = (float*)d_out;

    const int N = in_sizes[0] / 3;
    const int E = in_sizes[1] / 2;

    const float invN = 1.0f / (float)N;
    const int TB = 256;
    const int gN    = (N + TB - 1) / TB;
    const int gE    = (E + TB - 1) / TB;
    const int g32   = (N * 32 + TB - 1) / TB;
    const int gGemm = (N + BM - 1) / BM;
    const int nb    = (N + 1023) / 1024;

    // --- graph preprocessing ---
    detect_dtype_k<<<1, 32>>>(ei, E);
    init_deg_k<<<gN, TB>>>(N);
    count_deg_k<<<gE, TB>>>(ei, E);
    dinv_k<<<gN, TB>>>(N);
    scanA_k<<<nb, 1024>>>(N);
    scanB_k<<<1, 32>>>(nb);
    scanC_k<<<gN, TB>>>(N, E + N);
    scatter_k<<<gE, TB>>>(ei, E);
    zero_all_stats_k<<<(NSTATS * HF + TB - 1) / TB, TB>>>();

    // --- layer 0: conv1[0] -> raw agg in xs[0], stat 0 ---
    gemm3_k<<<g32, TB>>>(x, W0, N);
    agg128_k<<<2048, TB>>>(N, 0, 0);
    bnparam_k<<<1, 128>>>(0, g1, b1, invN);
    int cur = 0, curStat = 0;

    // --- up phase: i = 1..9 ---
    for (int i = 1; i <= 9; i++) {
        gemm128_k<<<gGemm, TB>>>(cur, curStat, -1, 0,
                                 Ws1 + (size_t)(i - 1) * HF * HF, N);
        int dst = (i < 9) ? i : 9;               // xs[i] or hA
        agg128_k<<<2048, TB>>>(N, dst, i);
        bnparam_k<<<1, 128>>>(i, g1 + (size_t)i * HF, b1 + (size_t)i * HF, invN);
        cur = dst; curStat = i;
    }

    // --- down phase: i = 0..7 (skip-add + both BN+ReLU fused into GEMM) ---
    int h = 9, hStat = 9;
    for (int i = 0; i < 8; i++) {
        int j = 8 - i;                           // xs[j], stat j
        gemm128_k<<<gGemm, TB>>>(h, hStat, j, j,
                                 Ws2 + (size_t)i * HF * HF, N);
        int nh = (h == 9) ? 10 : 9;
        int st = 10 + i;
        agg128_k<<<2048, TB>>>(N, nh, st);
        bnparam_k<<<1, 128>>>(st, g2 + (size_t)i * HF, b2 + (size_t)i * HF, invN);
        h = nh; hStat = st;
    }

    // --- final: out = sigmoid(conv(bnrelu(h) + bnrelu(xs0), Wout)) ---
    dot_out_k<<<g32, TB>>>(h, hStat, Wout, N);
    agg_sig_k<<<gN, TB>>>(out, N);
}